// round 1
// baseline (speedup 1.0000x reference)
#include <cuda_runtime.h>
#include <math_constants.h>

#define NPTS   8192
#define BATCH  2
#define BN_TOT (BATCH*NPTS)      /* 16384 */
#define KNB    20
#define M2     (BN_TOT*KNB)      /* 327680 */

/* ------------------------- device scratch ------------------------- */
__device__ float g_xa[BN_TOT*64];
__device__ float g_xb[BN_TOT*64];
__device__ float g_q [BN_TOT*64];
__device__ float g_k [BN_TOT*64];
__device__ float g_v [BN_TOT*64];
__device__ int   g_idx[M2];
__device__ float g_h1 [M2*64];
__device__ float g_inp[(size_t)M2*128];
__device__ float g_vnb[M2*64];
__device__ float g_sim[M2];
__device__ float g_part[BATCH*64*64];

/* ------------------------- embed: relu(points @ conv_w + b) -------- */
__global__ __launch_bounds__(256) void embed_kernel(
    const float* __restrict__ pts, const float* __restrict__ w,
    const float* __restrict__ b)
{
    int i = blockIdx.x*256 + threadIdx.x;       /* over BN_TOT*64 */
    int row = i >> 6, c = i & 63;
    float x = pts[row*3+0], y = pts[row*3+1], z = pts[row*3+2];
    float s = x*w[c] + y*w[64+c] + z*w[128+c] + b[c];
    g_xa[i] = fmaxf(s, 0.f);
}

/* ------------------------- KNN ------------------------------------ */
__device__ __forceinline__ bool kless(float d1,int i1,float d2,int i2){
    return d1 < d2 || (d1 == d2 && i1 < i2);
}

__global__ __launch_bounds__(256) void knn_kernel(const float* __restrict__ pts)
{
    const int SPL=8, QPB=32, TILE=256;
    __shared__ float4 sp[TILE];
    __shared__ float  sd[QPB][SPL*KNB];
    __shared__ int    si[QPB][SPL*KNB];
    int t = threadIdx.x;
    int qi = t >> 3, lane = t & 7;
    int gq = blockIdx.x*QPB + qi;               /* block stays in one batch */
    int b  = gq >> 13;
    const float* qp = pts + gq*3;
    float qx=qp[0], qy=qp[1], qz=qp[2];
    float bd[KNB]; int bi[KNB];
    #pragma unroll
    for (int p=0;p<KNB;p++){ bd[p]=CUDART_INF_F; bi[p]=0x7fffffff; }

    for (int t0=0; t0<NPTS; t0+=TILE){
        __syncthreads();
        {
            const float* pp = pts + (size_t)(b*NPTS + t0 + t)*3;
            sp[t] = make_float4(pp[0], pp[1], pp[2], 0.f);
        }
        __syncthreads();
        for (int c=lane; c<TILE; c+=SPL){
            float4 p = sp[c];
            float dx=qx-p.x, dy=qy-p.y, dz=qz-p.z;
            float d2 = dx*dx + dy*dy + dz*dz;
            int id = t0 + c;
            if (kless(d2, id, bd[KNB-1], bi[KNB-1])){
                float nd=d2; int ni=id; bool done=false;
                #pragma unroll
                for (int p=KNB-1; p>=1; --p){
                    bool sh = kless(nd, ni, bd[p-1], bi[p-1]);
                    if (!done){
                        bd[p] = sh ? bd[p-1] : nd;
                        bi[p] = sh ? bi[p-1] : ni;
                    }
                    done = done || !sh;
                }
                if (!done){ bd[0]=nd; bi[0]=ni; }
            }
        }
    }
    #pragma unroll
    for (int p=0;p<KNB;p++){ sd[qi][lane*KNB+p]=bd[p]; si[qi][lane*KNB+p]=bi[p]; }
    __syncthreads();
    if (lane == 0){
        int ptr[SPL];
        #pragma unroll
        for (int s=0;s<SPL;s++) ptr[s]=0;
        for (int r=0;r<KNB;r++){
            float best=CUDART_INF_F; int besti=0x7fffffff; int bs=0;
            #pragma unroll
            for (int s=0;s<SPL;s++){
                if (ptr[s] < KNB){
                    float d = sd[qi][s*KNB+ptr[s]];
                    int  ii = si[qi][s*KNB+ptr[s]];
                    if (kless(d, ii, best, besti)){ best=d; besti=ii; bs=s; }
                }
            }
            ptr[bs]++;
            g_idx[gq*KNB + r] = besti;
        }
    }
}

/* ------------------------- qkv GEMM (M=16384, K=64, N=192) -------- */
__global__ __launch_bounds__(256) void qkv_kernel(int xsel, const float* __restrict__ W)
{
    __shared__ float As[64][68];
    __shared__ float Bs[16][64];
    const float* X = xsel ? g_xb : g_xa;
    int t = threadIdx.x, tx = t & 15, ty = t >> 4;
    int bm0 = blockIdx.x * 64;
    int bn0 = blockIdx.y * 64;
    #pragma unroll
    for (int i=0;i<4;i++){
        int idx4 = t + i*256;
        int r = idx4 >> 4, c4 = idx4 & 15;
        *(float4*)&As[r][4*c4] = *(const float4*)&X[(size_t)(bm0+r)*64 + 4*c4];
    }
    float acc[4][4] = {};
    for (int ch=0; ch<64; ch+=16){
        __syncthreads();
        {
            int r = t >> 4, c4 = t & 15;
            *(float4*)&Bs[r][4*c4] = *(const float4*)&W[(ch+r)*192 + bn0 + 4*c4];
        }
        __syncthreads();
        #pragma unroll
        for (int k=0;k<16;k++){
            float a0=As[4*ty+0][ch+k], a1=As[4*ty+1][ch+k];
            float a2=As[4*ty+2][ch+k], a3=As[4*ty+3][ch+k];
            float4 bq = *(float4*)&Bs[k][4*tx];
            acc[0][0]+=a0*bq.x; acc[0][1]+=a0*bq.y; acc[0][2]+=a0*bq.z; acc[0][3]+=a0*bq.w;
            acc[1][0]+=a1*bq.x; acc[1][1]+=a1*bq.y; acc[1][2]+=a1*bq.z; acc[1][3]+=a1*bq.w;
            acc[2][0]+=a2*bq.x; acc[2][1]+=a2*bq.y; acc[2][2]+=a2*bq.z; acc[2][3]+=a2*bq.w;
            acc[3][0]+=a3*bq.x; acc[3][1]+=a3*bq.y; acc[3][2]+=a3*bq.z; acc[3][3]+=a3*bq.w;
        }
    }
    float* outp = (bn0 == 0) ? g_q : (bn0 == 64) ? g_k : g_v;
    #pragma unroll
    for (int i=0;i<4;i++){
        float4 o = make_float4(acc[i][0], acc[i][1], acc[i][2], acc[i][3]);
        *(float4*)&outp[(size_t)(bm0+4*ty+i)*64 + 4*tx] = o;
    }
}

/* ------------------------- h1 = relu(rel_pos @ pw1 + pb1) --------- */
__global__ __launch_bounds__(256) void h1_kernel(
    const float* __restrict__ pts, const float* __restrict__ w,
    const float* __restrict__ bias)
{
    int i = blockIdx.x*256 + threadIdx.x;       /* over M2*16 */
    int m = i >> 4, c0 = (i & 15) * 4;
    int gq = m / KNB;
    int b  = gq >> 13;
    int j  = g_idx[m];
    const float* pn = &pts[gq*3];
    const float* pj = &pts[(size_t)((b<<13)+j)*3];
    float rx = pn[0]-pj[0], ry = pn[1]-pj[1], rz = pn[2]-pj[2];
    float4 w0 = *(const float4*)&w[c0];
    float4 w1 = *(const float4*)&w[64+c0];
    float4 w2 = *(const float4*)&w[128+c0];
    float4 bb = *(const float4*)&bias[c0];
    float4 o;
    o.x = fmaxf(rx*w0.x + ry*w1.x + rz*w2.x + bb.x, 0.f);
    o.y = fmaxf(rx*w0.y + ry*w1.y + rz*w2.y + bb.y, 0.f);
    o.z = fmaxf(rx*w0.z + ry*w1.z + rz*w2.z + bb.z, 0.f);
    o.w = fmaxf(rx*w0.w + ry*w1.w + rz*w2.w + bb.w, 0.f);
    *(float4*)&g_h1[(size_t)m*64 + c0] = o;
}

/* ------- rpe = h1 @ pw2 + pb2, fused assembly of inp & vnb -------- */
__global__ __launch_bounds__(256) void rpe_kernel(
    const float* __restrict__ W, const float* __restrict__ pb2)
{
    __shared__ float As[64][68];
    __shared__ float Bs[16][64];
    int t = threadIdx.x, tx = t & 15, ty = t >> 4;
    int bm0 = blockIdx.x * 64;
    #pragma unroll
    for (int i=0;i<4;i++){
        int idx4 = t + i*256;
        int r = idx4 >> 4, c4 = idx4 & 15;
        *(float4*)&As[r][4*c4] = *(const float4*)&g_h1[(size_t)(bm0+r)*64 + 4*c4];
    }
    float acc[4][4] = {};
    for (int ch=0; ch<64; ch+=16){
        __syncthreads();
        {
            int r = t >> 4, c4 = t & 15;
            *(float4*)&Bs[r][4*c4] = *(const float4*)&W[(ch+r)*64 + 4*c4];
        }
        __syncthreads();
        #pragma unroll
        for (int k=0;k<16;k++){
            float a0=As[4*ty+0][ch+k], a1=As[4*ty+1][ch+k];
            float a2=As[4*ty+2][ch+k], a3=As[4*ty+3][ch+k];
            float4 bq = *(float4*)&Bs[k][4*tx];
            acc[0][0]+=a0*bq.x; acc[0][1]+=a0*bq.y; acc[0][2]+=a0*bq.z; acc[0][3]+=a0*bq.w;
            acc[1][0]+=a1*bq.x; acc[1][1]+=a1*bq.y; acc[1][2]+=a1*bq.z; acc[1][3]+=a1*bq.w;
            acc[2][0]+=a2*bq.x; acc[2][1]+=a2*bq.y; acc[2][2]+=a2*bq.z; acc[2][3]+=a2*bq.w;
            acc[3][0]+=a3*bq.x; acc[3][1]+=a3*bq.y; acc[3][2]+=a3*bq.z; acc[3][3]+=a3*bq.w;
        }
    }
    float4 pb = *(const float4*)&pb2[4*tx];
    #pragma unroll
    for (int i=0;i<4;i++){
        int m  = bm0 + 4*ty + i;
        int gq = m / KNB;
        int b  = gq >> 13;
        int jr = (b<<13) + g_idx[m];
        float4 rp = make_float4(acc[i][0]+pb.x, acc[i][1]+pb.y,
                                acc[i][2]+pb.z, acc[i][3]+pb.w);
        float4 qv = *(const float4*)&g_q[(size_t)gq*64 + 4*tx];
        float4 kv = *(const float4*)&g_k[(size_t)jr*64 + 4*tx];
        float4 vv = *(const float4*)&g_v[(size_t)jr*64 + 4*tx];
        float4 d  = make_float4(qv.x-kv.x, qv.y-kv.y, qv.z-kv.z, qv.w-kv.w);
        float4 vb = make_float4(vv.x+rp.x, vv.y+rp.y, vv.z+rp.z, vv.w+rp.w);
        *(float4*)&g_inp[(size_t)m*128 +      4*tx] = d;
        *(float4*)&g_inp[(size_t)m*128 + 64 + 4*tx] = rp;
        *(float4*)&g_vnb[(size_t)m*64  +      4*tx] = vb;
    }
}

/* --- sim = relu(inp @ aw1 + ab1) @ aw2 + ab2 (fully fused) -------- */
__global__ __launch_bounds__(256) void attn_kernel(
    const float* __restrict__ W, const float* __restrict__ ab1,
    const float* __restrict__ aw2, const float* __restrict__ ab2)
{
    __shared__ float As[64][132];
    __shared__ float Bs[16][64];
    __shared__ float red[64][17];
    int t = threadIdx.x, tx = t & 15, ty = t >> 4;
    int bm0 = blockIdx.x * 64;
    #pragma unroll
    for (int i=0;i<8;i++){
        int idx4 = t + i*256;
        int r = idx4 >> 5, c4 = idx4 & 31;
        *(float4*)&As[r][4*c4] = *(const float4*)&g_inp[(size_t)(bm0+r)*128 + 4*c4];
    }
    float rsum[4] = {0.f,0.f,0.f,0.f};
    for (int nb=0; nb<4; nb++){
        float acc[4][4] = {};
        for (int ch=0; ch<128; ch+=16){
            __syncthreads();
            {
                int r = t >> 4, c4 = t & 15;
                *(float4*)&Bs[r][4*c4] = *(const float4*)&W[(ch+r)*256 + nb*64 + 4*c4];
            }
            __syncthreads();
            #pragma unroll
            for (int k=0;k<16;k++){
                float a0=As[4*ty+0][ch+k], a1=As[4*ty+1][ch+k];
                float a2=As[4*ty+2][ch+k], a3=As[4*ty+3][ch+k];
                float4 bq = *(float4*)&Bs[k][4*tx];
                acc[0][0]+=a0*bq.x; acc[0][1]+=a0*bq.y; acc[0][2]+=a0*bq.z; acc[0][3]+=a0*bq.w;
                acc[1][0]+=a1*bq.x; acc[1][1]+=a1*bq.y; acc[1][2]+=a1*bq.z; acc[1][3]+=a1*bq.w;
                acc[2][0]+=a2*bq.x; acc[2][1]+=a2*bq.y; acc[2][2]+=a2*bq.z; acc[2][3]+=a2*bq.w;
                acc[3][0]+=a3*bq.x; acc[3][1]+=a3*bq.y; acc[3][2]+=a3*bq.z; acc[3][3]+=a3*bq.w;
            }
        }
        float4 bb = *(const float4*)&ab1[nb*64 + 4*tx];
        float4 a2 = *(const float4*)&aw2[nb*64 + 4*tx];
        #pragma unroll
        for (int i=0;i<4;i++){
            rsum[i] += fmaxf(acc[i][0]+bb.x, 0.f)*a2.x;
            rsum[i] += fmaxf(acc[i][1]+bb.y, 0.f)*a2.y;
            rsum[i] += fmaxf(acc[i][2]+bb.z, 0.f)*a2.z;
            rsum[i] += fmaxf(acc[i][3]+bb.w, 0.f)*a2.w;
        }
    }
    __syncthreads();
    #pragma unroll
    for (int i=0;i<4;i++) red[4*ty+i][tx] = rsum[i];
    __syncthreads();
    if (t < 64){
        float s = ab2[0];
        #pragma unroll
        for (int x=0;x<16;x++) s += red[t][x];
        g_sim[bm0 + t] = s;
    }
}

/* ---------------- softmax over K + weighted sum of v_nb ----------- */
__global__ __launch_bounds__(256) void softmax_kernel(int outsel)
{
    float* xout = outsel ? g_xb : g_xa;
    int gt = blockIdx.x*256 + threadIdx.x;
    int w = gt >> 5, lane = gt & 31;
    float s = (lane < KNB) ? g_sim[w*KNB + lane] : -CUDART_INF_F;
    float m = s;
    #pragma unroll
    for (int off=16; off; off>>=1) m = fmaxf(m, __shfl_xor_sync(0xffffffffu, m, off));
    float e = (lane < KNB) ? expf(s - m) : 0.f;
    float sum = e;
    #pragma unroll
    for (int off=16; off; off>>=1) sum += __shfl_xor_sync(0xffffffffu, sum, off);
    float attn = e / sum;
    float acc0 = 0.f, acc1 = 0.f;
    #pragma unroll
    for (int kk=0; kk<KNB; kk++){
        float a = __shfl_sync(0xffffffffu, attn, kk);
        const float* vb = &g_vnb[(size_t)(w*KNB + kk)*64];
        acc0 += a * vb[lane];
        acc1 += a * vb[32 + lane];
    }
    xout[(size_t)w*64 + lane]      = acc0;
    xout[(size_t)w*64 + 32 + lane] = acc1;
}

/* ---------------- global max pool (partial) ----------------------- */
__global__ void pool_kernel(void)
{
    int b = blockIdx.x, ch = blockIdx.y, c = threadIdx.x;  /* 64 threads */
    float m = -CUDART_INF_F;
    int base = b*NPTS + ch*128;
    #pragma unroll 4
    for (int n=0;n<128;n++) m = fmaxf(m, g_xa[(size_t)(base+n)*64 + c]);
    g_part[(b*64 + ch)*64 + c] = m;
}

/* ---------------- head: final max + fc1(relu) + fc3 --------------- */
__global__ void head_kernel(
    const float* __restrict__ fc1w, const float* __restrict__ fc1b,
    const float* __restrict__ fc3w, const float* __restrict__ fc3b,
    float* __restrict__ out)
{
    __shared__ float sp[BATCH*64];
    __shared__ float sh[BATCH*32];
    int t = threadIdx.x;
    if (t < 128){
        int b = t >> 6, c = t & 63;
        float m = -CUDART_INF_F;
        for (int ch=0; ch<64; ch++) m = fmaxf(m, g_part[(b*64+ch)*64 + c]);
        sp[b*64 + c] = m;
    }
    __syncthreads();
    if (t < 64){
        int b = t >> 5, cc = t & 31;
        float s = fc1b[cc];
        for (int c=0;c<64;c++) s += sp[b*64+c] * fc1w[c*32 + cc];
        sh[b*32 + cc] = fmaxf(s, 0.f);
    }
    __syncthreads();
    if (t < 6){
        int b = t / 3, o = t % 3;
        float s = fc3b[o];
        for (int cc=0;cc<32;cc++) s += sh[b*32+cc] * fc3w[cc*3 + o];
        out[b*3 + o] = s;
    }
}

/* ------------------------------ launch ---------------------------- */
extern "C" void kernel_launch(void* const* d_in, const int* in_sizes, int n_in,
                              void* d_out, int out_size)
{
    (void)in_sizes; (void)n_in; (void)out_size;
    const float* pts    = (const float*)d_in[0];
    const float* conv_w = (const float*)d_in[1];
    const float* conv_b = (const float*)d_in[2];
    float* out = (float*)d_out;

    embed_kernel<<<BN_TOT*64/256, 256>>>(pts, conv_w, conv_b);
    knn_kernel<<<BN_TOT/32, 256>>>(pts);

    /* layer 1: reads g_xa, writes g_xb */
    qkv_kernel<<<dim3(BN_TOT/64, 3), 256>>>(0, (const float*)d_in[3]);
    h1_kernel<<<M2*16/256, 256>>>(pts, (const float*)d_in[4], (const float*)d_in[5]);
    rpe_kernel<<<M2/64, 256>>>((const float*)d_in[6], (const float*)d_in[7]);
    attn_kernel<<<M2/64, 256>>>((const float*)d_in[8], (const float*)d_in[9],
                                (const float*)d_in[10], (const float*)d_in[11]);
    softmax_kernel<<<BN_TOT*32/256, 256>>>(1);

    /* layer 2: reads g_xb, writes g_xa */
    qkv_kernel<<<dim3(BN_TOT/64, 3), 256>>>(1, (const float*)d_in[12]);
    h1_kernel<<<M2*16/256, 256>>>(pts, (const float*)d_in[13], (const float*)d_in[14]);
    rpe_kernel<<<M2/64, 256>>>((const float*)d_in[15], (const float*)d_in[16]);
    attn_kernel<<<M2/64, 256>>>((const float*)d_in[17], (const float*)d_in[18],
                                (const float*)d_in[19], (const float*)d_in[20]);
    softmax_kernel<<<BN_TOT*32/256, 256>>>(0);

    pool_kernel<<<dim3(BATCH, 64), 64>>>();
    head_kernel<<<1, 128>>>((const float*)d_in[21], (const float*)d_in[22],
                            (const float*)d_in[23], (const float*)d_in[24], out);
}